// round 2
// baseline (speedup 1.0000x reference)
#include <cuda_runtime.h>
#include <cuda_bf16.h>
#include <cstdint>

// Problem constants
#define D_MODEL 1024
#define D_INNER 2048
#define D_STATE 16
#define D_CONV  4
#define DT_RANK 64
#define BATCH   2
#define SEQLEN  1024
#define NROWS   (BATCH * SEQLEN)          // 2048 "M" rows
#define NDBL    (DT_RANK + 2 * D_STATE)   // 96

// ---------------- scratch (device globals; no allocation) ----------------
__device__ float g_xz[(size_t)NROWS * 2 * D_INNER];     // (2048, 4096) x|z
__device__ float g_xc[(size_t)NROWS * D_INNER];         // (2048, 2048) conv+silu
__device__ float g_xdbl[(size_t)NROWS * NDBL];          // (2048, 96) dt|B|C (gated)
__device__ float g_gate[BATCH * NDBL];                  // (2, 96)
__device__ float g_delta[(size_t)NROWS * D_INNER];      // (2048, 2048)
__device__ float g_y[(size_t)NROWS * D_INNER];          // (2048, 2048)

// ---------------- generic fp32 NT GEMM: C[M,N] = A[M,K] * B[N,K]^T ----------------
// act: 0 = none, 1 = softplus(v + bias)
// colscale: if non-null, v *= colscale[(row / rows_per_batch) * N + col]
#define TM 128
#define TN 128
#define TK 16

__global__ __launch_bounds__(256) void gemm_nt(
    const float* __restrict__ A, int lda,
    const float* __restrict__ B, int ldb,
    float* __restrict__ C, int ldc,
    int M, int N, int K,
    const float* __restrict__ bias, int act,
    const float* __restrict__ colscale, int rows_per_batch)
{
    __shared__ float As[2][TK][TM];
    __shared__ float Bs[2][TK][TN];

    const int tid = threadIdx.x;
    const int tx = tid & 15;          // 0..15 -> N direction
    const int ty = tid >> 4;          // 0..15 -> M direction
    const int row0 = blockIdx.y * TM;
    const int col0 = blockIdx.x * TN;

    // per-thread load slots (2 float4 each for A and B tile)
    const int r_a0 = tid >> 1;                 // 0..127
    const int kc_a0 = (tid & 1) << 3;          // 0 or 8 -> two float4 at +0,+4
    float acc[8][8];
#pragma unroll
    for (int i = 0; i < 8; i++)
#pragma unroll
        for (int j = 0; j < 8; j++) acc[i][j] = 0.f;

    auto load_tile = [&](int k0, int buf) {
        // A tile: each thread loads 2 consecutive float4 (8 floats along K)
        {
            int gr = row0 + r_a0;
            float4 v0 = make_float4(0.f,0.f,0.f,0.f), v1 = v0;
            if (gr < M) {
                const float* p = A + (size_t)gr * lda + k0 + kc_a0;
                v0 = *(const float4*)(p);
                v1 = *(const float4*)(p + 4);
            }
            As[buf][kc_a0 + 0][r_a0] = v0.x; As[buf][kc_a0 + 1][r_a0] = v0.y;
            As[buf][kc_a0 + 2][r_a0] = v0.z; As[buf][kc_a0 + 3][r_a0] = v0.w;
            As[buf][kc_a0 + 4][r_a0] = v1.x; As[buf][kc_a0 + 5][r_a0] = v1.y;
            As[buf][kc_a0 + 6][r_a0] = v1.z; As[buf][kc_a0 + 7][r_a0] = v1.w;
        }
        {
            int gc = col0 + r_a0;
            float4 v0 = make_float4(0.f,0.f,0.f,0.f), v1 = v0;
            if (gc < N) {
                const float* p = B + (size_t)gc * ldb + k0 + kc_a0;
                v0 = *(const float4*)(p);
                v1 = *(const float4*)(p + 4);
            }
            Bs[buf][kc_a0 + 0][r_a0] = v0.x; Bs[buf][kc_a0 + 1][r_a0] = v0.y;
            Bs[buf][kc_a0 + 2][r_a0] = v0.z; Bs[buf][kc_a0 + 3][r_a0] = v0.w;
            Bs[buf][kc_a0 + 4][r_a0] = v1.x; Bs[buf][kc_a0 + 5][r_a0] = v1.y;
            Bs[buf][kc_a0 + 6][r_a0] = v1.z; Bs[buf][kc_a0 + 7][r_a0] = v1.w;
        }
    };

    load_tile(0, 0);
    __syncthreads();

    int nk = K / TK;
    for (int kt = 0; kt < nk; kt++) {
        int cur = kt & 1;
        if (kt + 1 < nk) load_tile((kt + 1) * TK, cur ^ 1);

#pragma unroll
        for (int kk = 0; kk < TK; kk++) {
            float a[8], b[8];
            float4 a0 = *(const float4*)&As[cur][kk][ty * 8];
            float4 a1 = *(const float4*)&As[cur][kk][ty * 8 + 4];
            float4 b0 = *(const float4*)&Bs[cur][kk][tx * 8];
            float4 b1 = *(const float4*)&Bs[cur][kk][tx * 8 + 4];
            a[0] = a0.x; a[1] = a0.y; a[2] = a0.z; a[3] = a0.w;
            a[4] = a1.x; a[5] = a1.y; a[6] = a1.z; a[7] = a1.w;
            b[0] = b0.x; b[1] = b0.y; b[2] = b0.z; b[3] = b0.w;
            b[4] = b1.x; b[5] = b1.y; b[6] = b1.z; b[7] = b1.w;
#pragma unroll
            for (int i = 0; i < 8; i++)
#pragma unroll
                for (int j = 0; j < 8; j++) acc[i][j] += a[i] * b[j];
        }
        __syncthreads();
    }

    // epilogue
#pragma unroll
    for (int i = 0; i < 8; i++) {
        int row = row0 + ty * 8 + i;
        if (row >= M) continue;
        int batch = (rows_per_batch > 0) ? (row / rows_per_batch) : 0;
#pragma unroll
        for (int j = 0; j < 8; j++) {
            int col = col0 + tx * 8 + j;
            if (col >= N) continue;
            float v = acc[i][j];
            if (bias) v += bias[col];
            if (act == 1) {
                // softplus, numerically stable
                v = (v > 20.f) ? v : log1pf(__expf(v));
            }
            if (colscale) v *= colscale[batch * N + col];
            C[(size_t)row * ldc + col] = v;
        }
    }
}

// ---------------- causal depthwise conv (k=4) + SiLU ----------------
__global__ void conv_silu_kernel(const float* __restrict__ conv_w,
                                 const float* __restrict__ conv_b)
{
    int idx = blockIdx.x * blockDim.x + threadIdx.x;
    int total = BATCH * SEQLEN * D_INNER;
    if (idx >= total) return;
    int d = idx & (D_INNER - 1);
    int l = (idx >> 11) & (SEQLEN - 1);
    int b = idx >> 21;

    float w0 = conv_w[d * 4 + 0], w1 = conv_w[d * 4 + 1];
    float w2 = conv_w[d * 4 + 2], w3 = conv_w[d * 4 + 3];
    const float* xrow = g_xz + ((size_t)(b * SEQLEN) * (2 * D_INNER)) + d;
    float acc = conv_b[d];
    if (l >= 3) acc += xrow[(size_t)(l - 3) * (2 * D_INNER)] * w0;
    if (l >= 2) acc += xrow[(size_t)(l - 2) * (2 * D_INNER)] * w1;
    if (l >= 1) acc += xrow[(size_t)(l - 1) * (2 * D_INNER)] * w2;
    acc += xrow[(size_t)l * (2 * D_INNER)] * w3;
    // silu
    float s = acc / (1.f + __expf(-acc));
    g_xc[(size_t)(b * SEQLEN + l) * D_INNER + d] = s;
}

// ---------------- text gate: sigmoid(x_text @ gate_w^T + gate_b) ----------------
__global__ void gate_kernel(const float* __restrict__ x_text,
                            const float* __restrict__ gate_w,
                            const float* __restrict__ gate_b)
{
    int t = threadIdx.x;             // 0..191
    if (t >= BATCH * NDBL) return;
    int b = t / NDBL;
    int j = t % NDBL;
    const float* xr = x_text + b * D_MODEL;
    const float* wr = gate_w + (size_t)j * D_MODEL;
    float acc = gate_b[j];
    for (int k = 0; k < D_MODEL; k += 4) {
        float4 xv = *(const float4*)(xr + k);
        float4 wv = *(const float4*)(wr + k);
        acc += xv.x * wv.x + xv.y * wv.y + xv.z * wv.z + xv.w * wv.w;
    }
    g_gate[b * NDBL + j] = 1.f / (1.f + __expf(-acc));
}

// ---------------- selective scan + fused epilogue ----------------
// thread = one (b, d, n); 16-lane shfl reduction; lane n==0 writes
// y = (sum_n h*C + D*xc) * silu(z)
__global__ __launch_bounds__(256) void scan_kernel(const float* __restrict__ A_log,
                                                   const float* __restrict__ Dp)
{
    int g = blockIdx.x * blockDim.x + threadIdx.x;  // 0..65535
    int n = g & 15;
    int pair = g >> 4;
    int d = pair & (D_INNER - 1);
    int b = pair >> 11;

    float An = -__expf(A_log[d * D_STATE + n]);
    float Dd = Dp[d];
    float h = 0.f;

    const float* dptr = g_delta + (size_t)b * SEQLEN * D_INNER + d;
    const float* uptr = g_xc + (size_t)b * SEQLEN * D_INNER + d;
    const float* bcp = g_xdbl + (size_t)b * SEQLEN * NDBL + DT_RANK;
    const float* zptr = g_xz + (size_t)b * SEQLEN * (2 * D_INNER) + D_INNER + d;
    float* yptr = g_y + (size_t)b * SEQLEN * D_INNER + d;

    // prefetch t=0
    float dl = dptr[0];
    float u = uptr[0];
    float Bn = bcp[n];
    float Cn = bcp[D_STATE + n];

    for (int t = 0; t < SEQLEN; t++) {
        float dl_c = dl, u_c = u, Bn_c = Bn, Cn_c = Cn;
        if (t + 1 < SEQLEN) {
            size_t o = (size_t)(t + 1);
            dl = dptr[o * D_INNER];
            u = uptr[o * D_INNER];
            Bn = bcp[o * NDBL + n];
            Cn = bcp[o * NDBL + D_STATE + n];
        }
        float a = __expf(dl_c * An);
        h = h * a + dl_c * u_c * Bn_c;
        float p = h * Cn_c;
        p += __shfl_xor_sync(0xffffffffu, p, 8, 16);
        p += __shfl_xor_sync(0xffffffffu, p, 4, 16);
        p += __shfl_xor_sync(0xffffffffu, p, 2, 16);
        p += __shfl_xor_sync(0xffffffffu, p, 1, 16);
        if (n == 0) {
            float z = zptr[(size_t)t * (2 * D_INNER)];
            float sz = z / (1.f + __expf(-z));
            yptr[(size_t)t * D_INNER] = (p + Dd * u_c) * sz;
        }
    }
}

// ---------------- launcher ----------------
extern "C" void kernel_launch(void* const* d_in, const int* in_sizes, int n_in,
                              void* d_out, int out_size)
{
    const float* hidden    = (const float*)d_in[0];
    const float* x_text    = (const float*)d_in[1];
    const float* in_proj_w = (const float*)d_in[2];
    const float* conv_w    = (const float*)d_in[3];
    const float* conv_b    = (const float*)d_in[4];
    const float* x_proj_w  = (const float*)d_in[5];
    const float* dt_proj_w = (const float*)d_in[6];
    const float* dt_proj_b = (const float*)d_in[7];
    const float* A_log     = (const float*)d_in[8];
    const float* Dp        = (const float*)d_in[9];
    const float* out_proj_w= (const float*)d_in[10];
    const float* gate_w    = (const float*)d_in[11];
    const float* gate_b    = (const float*)d_in[12];
    float* out = (float*)d_out;

    float *xz, *xc, *xdbl, *gate, *delta, *ybuf;
    cudaGetSymbolAddress((void**)&xz, g_xz);
    cudaGetSymbolAddress((void**)&xc, g_xc);
    cudaGetSymbolAddress((void**)&xdbl, g_xdbl);
    cudaGetSymbolAddress((void**)&gate, g_gate);
    cudaGetSymbolAddress((void**)&delta, g_delta);
    cudaGetSymbolAddress((void**)&ybuf, g_y);

    // G1: xz = hidden @ in_proj_w^T   (2048 x 4096, K=1024)
    {
        dim3 grid((2 * D_INNER + TN - 1) / TN, (NROWS + TM - 1) / TM);
        gemm_nt<<<grid, 256>>>(hidden, D_MODEL, in_proj_w, D_MODEL,
                               xz, 2 * D_INNER, NROWS, 2 * D_INNER, D_MODEL,
                               nullptr, 0, nullptr, 0);
    }
    // gate (tiny)
    gate_kernel<<<1, 192>>>(x_text, gate_w, gate_b);
    // conv + silu
    {
        int total = BATCH * SEQLEN * D_INNER;
        conv_silu_kernel<<<(total + 255) / 256, 256>>>(conv_w, conv_b);
    }
    // G2: x_dbl = (xc @ x_proj_w^T) * gate   (2048 x 96, K=2048)
    {
        dim3 grid((NDBL + TN - 1) / TN, (NROWS + TM - 1) / TM);
        gemm_nt<<<grid, 256>>>(xc, D_INNER, x_proj_w, D_INNER,
                               xdbl, NDBL, NROWS, NDBL, D_INNER,
                               nullptr, 0, gate, SEQLEN);
    }
    // G3: delta = softplus(dt @ dt_proj_w^T + dt_proj_b)   (2048 x 2048, K=64)
    {
        dim3 grid((D_INNER + TN - 1) / TN, (NROWS + TM - 1) / TM);
        gemm_nt<<<grid, 256>>>(xdbl, NDBL, dt_proj_w, DT_RANK,
                               delta, D_INNER, NROWS, D_INNER, DT_RANK,
                               dt_proj_b, 1, nullptr, 0);
    }
    // scan + fused (D*xc, silu(z)) epilogue
    scan_kernel<<<(BATCH * D_INNER * D_STATE) / 256, 256>>>(A_log, Dp);
    // G4: out = y @ out_proj_w^T   (2048 x 1024, K=2048)
    {
        dim3 grid((D_MODEL + TN - 1) / TN, (NROWS + TM - 1) / TM);
        gemm_nt<<<grid, 256>>>(ybuf, D_INNER, out_proj_w, D_INNER,
                               out, D_MODEL, NROWS, D_MODEL, D_INNER,
                               nullptr, 0, nullptr, 0);
    }
}

// round 4
// speedup vs baseline: 1.5264x; 1.5264x over previous
#include <cuda_runtime.h>
#include <cuda_bf16.h>
#include <cstdint>

// Problem constants
#define D_MODEL 1024
#define D_INNER 2048
#define D_STATE 16
#define D_CONV  4
#define DT_RANK 64
#define BATCH   2
#define SEQLEN  1024
#define NROWS   (BATCH * SEQLEN)          // 2048 "M" rows
#define NDBL    (DT_RANK + 2 * D_STATE)   // 96

// ---------------- scratch (device globals; no allocation) ----------------
__device__ float g_xz[(size_t)NROWS * 2 * D_INNER];     // (2048, 4096) x|z
__device__ float g_xc[(size_t)NROWS * D_INNER];         // (2048, 2048) conv+silu
__device__ float g_xdbl[(size_t)NROWS * NDBL];          // (2048, 96) dt|B|C
__device__ float g_gate[BATCH * NDBL];                  // (2, 96)
__device__ float g_delta[(size_t)NROWS * D_INNER];      // (2048, 2048)
__device__ float g_y[(size_t)NROWS * D_INNER];          // (2048, 2048)

// ---------------- mma helpers (legacy tensor core path; PTX sm_80 baseline) ----
__device__ __forceinline__ uint32_t f2tf32(float x) {
    uint32_t r;
    asm("cvt.rna.tf32.f32 %0, %1;" : "=r"(r) : "f"(x));
    return r;
}

__device__ __forceinline__ void mma_tf32(float c[4], const uint32_t a[4],
                                         const uint32_t b[2]) {
    asm volatile(
        "mma.sync.aligned.m16n8k8.row.col.f32.tf32.tf32.f32 "
        "{%0,%1,%2,%3}, {%4,%5,%6,%7}, {%8,%9}, {%0,%1,%2,%3};"
        : "+f"(c[0]), "+f"(c[1]), "+f"(c[2]), "+f"(c[3])
        : "r"(a[0]), "r"(a[1]), "r"(a[2]), "r"(a[3]), "r"(b[0]), "r"(b[1]));
}

// ---------------- tensor-core tf32 NT GEMM: C[M,N] = A[M,K] * B[N,K]^T ------
// Tile 128x128, K staged 32 at a time. 256 threads = 8 warps (2 x 4),
// warp tile 64(m) x 32(n), mma m16n8k8 fragments.
// Smem is fragment-packed:
//   A elem (m,k): mf=m>>4, kc=k>>3, lane=(m&7)*4+(k&3), j=((k>>2&1)<<1)|(m>>3&1)
//     sA[ (mf*4+kc)*128 + lane*4 + j ]
//   B elem (n,k): nf=n>>3, kc=k>>3, lane part=(n&7)*8+(k&3)*2, j=(k>>2)&1
//     sB[ (nf*4+kc)*64 + (n&7)*8 + (k&3)*2 + j ]
// act: 0=none, 1=softplus(v+bias). atomic: accumulate with atomicAdd (split-K).
__global__ __launch_bounds__(256, 2)
void gemm_mma(const float* __restrict__ A, int lda,
              const float* __restrict__ B, int ldb,
              float* __restrict__ C, int ldc,
              int M, int N, int K,
              const float* __restrict__ bias, int act, int atomic)
{
    __shared__ uint32_t sA[4096];   // 16 KB
    __shared__ uint32_t sB[4096];   // 16 KB

    const int tid = threadIdx.x;
    const int wid = tid >> 5;
    const int lane = tid & 31;
    const int warp_m = wid >> 2;          // 0..1
    const int warp_n = wid & 3;           // 0..3
    const int row0 = blockIdx.y * 128;
    const int col0 = blockIdx.x * 128;

    // split-K
    const int kper = K / gridDim.z;
    const int kbeg = blockIdx.z * kper;

    // staging identity: this thread stages A row rA, B row nB, col half cb
    const int rA = tid >> 1;              // 0..127
    const int cb = (tid & 1) * 16;        // 0 or 16
    const int Abase = (rA >> 4) * 512 + (rA & 7) * 16 + ((rA >> 3) & 1);
    const int Bbase = (rA >> 3) * 256 + (rA & 7) * 8;

    float acc[4][4][4];
#pragma unroll
    for (int mi = 0; mi < 4; mi++)
#pragma unroll
        for (int ni = 0; ni < 4; ni++)
#pragma unroll
            for (int e = 0; e < 4; e++) acc[mi][ni][e] = 0.f;

    const int nstages = kper >> 5;
    for (int s = 0; s < nstages; s++) {
        const int k0 = kbeg + (s << 5);

        // ---- stage A (rows always valid: M % 128 == 0) ----
        {
            const float* ap = A + (size_t)(row0 + rA) * lda + k0 + cb;
#pragma unroll
            for (int p = 0; p < 4; p++) {
                float4 v = *(const float4*)(ap + p * 4);
                int kc = (cb + p * 4) >> 3;
                int jh = ((cb >> 2) + p) & 1;
                int base = Abase + kc * 128 + jh * 2;
                sA[base + 0]  = f2tf32(v.x);
                sA[base + 4]  = f2tf32(v.y);
                sA[base + 8]  = f2tf32(v.z);
                sA[base + 12] = f2tf32(v.w);
            }
        }
        // ---- stage B (guard ragged N) ----
        {
            const int gc = col0 + rA;
            const bool ok = (gc < N);
            const float* bp = B + (size_t)gc * ldb + k0 + cb;
#pragma unroll
            for (int p = 0; p < 4; p++) {
                float4 v = ok ? *(const float4*)(bp + p * 4)
                              : make_float4(0.f, 0.f, 0.f, 0.f);
                int kc = (cb + p * 4) >> 3;
                int j = ((cb >> 2) + p) & 1;
                int base = Bbase + kc * 64 + j;
                sB[base + 0] = f2tf32(v.x);
                sB[base + 2] = f2tf32(v.y);
                sB[base + 4] = f2tf32(v.z);
                sB[base + 6] = f2tf32(v.w);
            }
        }
        __syncthreads();

        // ---- mainloop: 4 k-chunks of 8 ----
#pragma unroll
        for (int kc = 0; kc < 4; kc++) {
            uint4 af[4];
            uint2 bf[4];
#pragma unroll
            for (int mi = 0; mi < 4; mi++)
                af[mi] = *(const uint4*)&sA[((warp_m * 4 + mi) * 4 + kc) * 128 + lane * 4];
#pragma unroll
            for (int ni = 0; ni < 4; ni++)
                bf[ni] = *(const uint2*)&sB[((warp_n * 4 + ni) * 4 + kc) * 64 + lane * 2];
#pragma unroll
            for (int mi = 0; mi < 4; mi++)
#pragma unroll
                for (int ni = 0; ni < 4; ni++)
                    mma_tf32(acc[mi][ni], (const uint32_t*)&af[mi],
                             (const uint32_t*)&bf[ni]);
        }
        __syncthreads();
    }

    // ---- epilogue ----
    const int r_lo = row0 + warp_m * 64 + (lane >> 2);
    const int c_lo = col0 + warp_n * 32 + (lane & 3) * 2;
    if (atomic) {
#pragma unroll
        for (int mi = 0; mi < 4; mi++) {
#pragma unroll
            for (int ni = 0; ni < 4; ni++) {
                int row = r_lo + mi * 16;
                int col = c_lo + ni * 8;
                if (col < N) {
                    atomicAdd(C + (size_t)row * ldc + col, acc[mi][ni][0]);
                    atomicAdd(C + (size_t)(row + 8) * ldc + col, acc[mi][ni][2]);
                }
                if (col + 1 < N) {
                    atomicAdd(C + (size_t)row * ldc + col + 1, acc[mi][ni][1]);
                    atomicAdd(C + (size_t)(row + 8) * ldc + col + 1, acc[mi][ni][3]);
                }
            }
        }
    } else {
        // non-atomic callers always have full tiles (N % 128 == 0)
#pragma unroll
        for (int mi = 0; mi < 4; mi++) {
#pragma unroll
            for (int ni = 0; ni < 4; ni++) {
                int row = r_lo + mi * 16;
                int col = c_lo + ni * 8;
                float v0 = acc[mi][ni][0], v1 = acc[mi][ni][1];
                float v2 = acc[mi][ni][2], v3 = acc[mi][ni][3];
                if (bias) {
                    float b0 = bias[col], b1 = bias[col + 1];
                    v0 += b0; v1 += b1; v2 += b0; v3 += b1;
                }
                if (act == 1) {
                    v0 = (v0 > 20.f) ? v0 : log1pf(__expf(v0));
                    v1 = (v1 > 20.f) ? v1 : log1pf(__expf(v1));
                    v2 = (v2 > 20.f) ? v2 : log1pf(__expf(v2));
                    v3 = (v3 > 20.f) ? v3 : log1pf(__expf(v3));
                }
                *(float2*)(C + (size_t)row * ldc + col) = make_float2(v0, v1);
                *(float2*)(C + (size_t)(row + 8) * ldc + col) = make_float2(v2, v3);
            }
        }
    }
}

// ---------------- zero g_xdbl (for split-K atomic accumulation) ----------------
__global__ void zero_xdbl_kernel()
{
    int idx = blockIdx.x * blockDim.x + threadIdx.x;
    if (idx < NROWS * NDBL) g_xdbl[idx] = 0.f;
}

// ---------------- apply text gate to x_dbl in place ----------------
__global__ void gate_apply_kernel()
{
    int idx = blockIdx.x * blockDim.x + threadIdx.x;
    if (idx >= NROWS * NDBL) return;
    int row = idx / NDBL;
    int j = idx - row * NDBL;
    int batch = row >> 10;                 // row / SEQLEN
    g_xdbl[idx] *= g_gate[batch * NDBL + j];
}

// ---------------- causal depthwise conv (k=4) + SiLU ----------------
__global__ void conv_silu_kernel(const float* __restrict__ conv_w,
                                 const float* __restrict__ conv_b)
{
    int idx = blockIdx.x * blockDim.x + threadIdx.x;
    int total = BATCH * SEQLEN * D_INNER;
    if (idx >= total) return;
    int d = idx & (D_INNER - 1);
    int l = (idx >> 11) & (SEQLEN - 1);
    int b = idx >> 21;

    float w0 = conv_w[d * 4 + 0], w1 = conv_w[d * 4 + 1];
    float w2 = conv_w[d * 4 + 2], w3 = conv_w[d * 4 + 3];
    const float* xrow = g_xz + ((size_t)(b * SEQLEN) * (2 * D_INNER)) + d;
    float acc = conv_b[d];
    if (l >= 3) acc += xrow[(size_t)(l - 3) * (2 * D_INNER)] * w0;
    if (l >= 2) acc += xrow[(size_t)(l - 2) * (2 * D_INNER)] * w1;
    if (l >= 1) acc += xrow[(size_t)(l - 1) * (2 * D_INNER)] * w2;
    acc += xrow[(size_t)l * (2 * D_INNER)] * w3;
    float s = acc / (1.f + __expf(-acc));
    g_xc[(size_t)(b * SEQLEN + l) * D_INNER + d] = s;
}

// ---------------- text gate: sigmoid(x_text @ gate_w^T + gate_b) ----------------
__global__ void gate_kernel(const float* __restrict__ x_text,
                            const float* __restrict__ gate_w,
                            const float* __restrict__ gate_b)
{
    int t = threadIdx.x;             // 0..191
    if (t >= BATCH * NDBL) return;
    int b = t / NDBL;
    int j = t % NDBL;
    const float* xr = x_text + b * D_MODEL;
    const float* wr = gate_w + (size_t)j * D_MODEL;
    float acc = gate_b[j];
    for (int k = 0; k < D_MODEL; k += 4) {
        float4 xv = *(const float4*)(xr + k);
        float4 wv = *(const float4*)(wr + k);
        acc += xv.x * wv.x + xv.y * wv.y + xv.z * wv.z + xv.w * wv.w;
    }
    g_gate[b * NDBL + j] = 1.f / (1.f + __expf(-acc));
}

// ---------------- selective scan + fused epilogue ----------------
__global__ __launch_bounds__(256) void scan_kernel(const float* __restrict__ A_log,
                                                   const float* __restrict__ Dp)
{
    int g = blockIdx.x * blockDim.x + threadIdx.x;  // 0..65535
    int n = g & 15;
    int pair = g >> 4;
    int d = pair & (D_INNER - 1);
    int b = pair >> 11;

    float An = -__expf(A_log[d * D_STATE + n]);
    float Dd = Dp[d];
    float h = 0.f;

    const float* dptr = g_delta + (size_t)b * SEQLEN * D_INNER + d;
    const float* uptr = g_xc + (size_t)b * SEQLEN * D_INNER + d;
    const float* bcp = g_xdbl + (size_t)b * SEQLEN * NDBL + DT_RANK;
    const float* zptr = g_xz + (size_t)b * SEQLEN * (2 * D_INNER) + D_INNER + d;
    float* yptr = g_y + (size_t)b * SEQLEN * D_INNER + d;

    float dl = dptr[0];
    float u = uptr[0];
    float Bn = bcp[n];
    float Cn = bcp[D_STATE + n];

    for (int t = 0; t < SEQLEN; t++) {
        float dl_c = dl, u_c = u, Bn_c = Bn, Cn_c = Cn;
        if (t + 1 < SEQLEN) {
            size_t o = (size_t)(t + 1);
            dl = dptr[o * D_INNER];
            u = uptr[o * D_INNER];
            Bn = bcp[o * NDBL + n];
            Cn = bcp[o * NDBL + D_STATE + n];
        }
        float a = __expf(dl_c * An);
        h = h * a + dl_c * u_c * Bn_c;
        float p = h * Cn_c;
        p += __shfl_xor_sync(0xffffffffu, p, 8, 16);
        p += __shfl_xor_sync(0xffffffffu, p, 4, 16);
        p += __shfl_xor_sync(0xffffffffu, p, 2, 16);
        p += __shfl_xor_sync(0xffffffffu, p, 1, 16);
        if (n == 0) {
            float z = zptr[(size_t)t * (2 * D_INNER)];
            float sz = z / (1.f + __expf(-z));
            yptr[(size_t)t * D_INNER] = (p + Dd * u_c) * sz;
        }
    }
}

// ---------------- launcher ----------------
extern "C" void kernel_launch(void* const* d_in, const int* in_sizes, int n_in,
                              void* d_out, int out_size)
{
    const float* hidden    = (const float*)d_in[0];
    const float* x_text    = (const float*)d_in[1];
    const float* in_proj_w = (const float*)d_in[2];
    const float* conv_w    = (const float*)d_in[3];
    const float* conv_b    = (const float*)d_in[4];
    const float* x_proj_w  = (const float*)d_in[5];
    const float* dt_proj_w = (const float*)d_in[6];
    const float* dt_proj_b = (const float*)d_in[7];
    const float* A_log     = (const float*)d_in[8];
    const float* Dp        = (const float*)d_in[9];
    const float* out_proj_w= (const float*)d_in[10];
    const float* gate_w    = (const float*)d_in[11];
    const float* gate_b    = (const float*)d_in[12];
    float* out = (float*)d_out;

    float *xz, *xc, *xdbl, *delta, *ybuf;
    cudaGetSymbolAddress((void**)&xz, g_xz);
    cudaGetSymbolAddress((void**)&xc, g_xc);
    cudaGetSymbolAddress((void**)&xdbl, g_xdbl);
    cudaGetSymbolAddress((void**)&delta, g_delta);
    cudaGetSymbolAddress((void**)&ybuf, g_y);

    // G1: xz = hidden @ in_proj_w^T   (2048 x 4096, K=1024)
    {
        dim3 grid(2 * D_INNER / 128, NROWS / 128, 1);
        gemm_mma<<<grid, 256>>>(hidden, D_MODEL, in_proj_w, D_MODEL,
                                xz, 2 * D_INNER, NROWS, 2 * D_INNER, D_MODEL,
                                nullptr, 0, 0);
    }
    // gate (tiny)
    gate_kernel<<<1, 192>>>(x_text, gate_w, gate_b);
    // conv + silu
    {
        int total = BATCH * SEQLEN * D_INNER;
        conv_silu_kernel<<<(total + 255) / 256, 256>>>(conv_w, conv_b);
    }
    // zero x_dbl for split-K accumulation
    zero_xdbl_kernel<<<(NROWS * NDBL + 255) / 256, 256>>>();
    // G2: x_dbl = xc @ x_proj_w^T   (2048 x 96, K=2048) split-K=8, atomic
    {
        dim3 grid(1, NROWS / 128, 8);
        gemm_mma<<<grid, 256>>>(xc, D_INNER, x_proj_w, D_INNER,
                                xdbl, NDBL, NROWS, NDBL, D_INNER,
                                nullptr, 0, 1);
    }
    // apply text gate to x_dbl
    gate_apply_kernel<<<(NROWS * NDBL + 255) / 256, 256>>>();
    // G3: delta = softplus(dt @ dt_proj_w^T + dt_proj_b)   (2048 x 2048, K=64)
    {
        dim3 grid(D_INNER / 128, NROWS / 128, 1);
        gemm_mma<<<grid, 256>>>(xdbl, NDBL, dt_proj_w, DT_RANK,
                                delta, D_INNER, NROWS, D_INNER, DT_RANK,
                                dt_proj_b, 1, 0);
    }
    // scan + fused (D*xc, silu(z)) epilogue
    scan_kernel<<<(BATCH * D_INNER * D_STATE) / 256, 256>>>(A_log, Dp);
    // G4: out = y @ out_proj_w^T   (2048 x 1024, K=2048)
    {
        dim3 grid(D_MODEL / 128, NROWS / 128, 1);
        gemm_mma<<<grid, 256>>>(ybuf, D_INNER, out_proj_w, D_INNER,
                                out, D_MODEL, NROWS, D_MODEL, D_INNER,
                                nullptr, 0, 0);
    }
}

// round 5
// speedup vs baseline: 1.8837x; 1.2340x over previous
#include <cuda_runtime.h>
#include <cuda_bf16.h>
#include <cstdint>

// Problem constants
#define D_MODEL 1024
#define D_INNER 2048
#define D_STATE 16
#define D_CONV  4
#define DT_RANK 64
#define BATCH   2
#define SEQLEN  1024
#define NROWS   (BATCH * SEQLEN)          // 2048 "M" rows
#define NDBL    (DT_RANK + 2 * D_STATE)   // 96

// ---------------- scratch (device globals; no allocation) ----------------
__device__ float g_xz[(size_t)NROWS * 2 * D_INNER];     // (2048, 4096) x|z
__device__ float g_xc[(size_t)NROWS * D_INNER];         // (2048, 2048) conv+silu
__device__ float g_xdbl[(size_t)NROWS * NDBL];          // (2048, 96) dt|B|C
__device__ float g_gate[BATCH * NDBL];                  // (2, 96)
__device__ float g_delta[(size_t)NROWS * D_INNER];      // (2048, 2048)

// packed tf32 operand tiles: [tileM(or N)/128][K/32][4096 words]
__device__ uint32_t g_hid_p[(size_t)NROWS * D_MODEL];            // A of G1
__device__ uint32_t g_w1_p[(size_t)2 * D_INNER * D_MODEL];       // B of G1
__device__ uint32_t g_xc_p[(size_t)NROWS * D_INNER];             // A of G2
__device__ uint32_t g_w2_p[(size_t)128 * D_INNER];               // B of G2 (pad 96->128)
__device__ uint32_t g_dt_p[(size_t)NROWS * DT_RANK];             // A of G3
__device__ uint32_t g_w3_p[(size_t)D_INNER * DT_RANK];           // B of G3
__device__ uint32_t g_y_p[(size_t)NROWS * D_INNER];              // A of G4
__device__ uint32_t g_w4_p[(size_t)D_MODEL * D_INNER];           // B of G4

// ---------------- helpers ----------------
__device__ __forceinline__ uint32_t f2tf32(float x) {
    uint32_t r;
    asm("cvt.rna.tf32.f32 %0, %1;" : "=r"(r) : "f"(x));
    return r;
}

__device__ __forceinline__ uint32_t smem_u32(const void* p) {
    uint32_t a;
    asm("{ .reg .u64 t; cvta.to.shared.u64 t, %1; cvt.u32.u64 %0, t; }"
        : "=r"(a) : "l"(p));
    return a;
}

__device__ __forceinline__ void mma_tf32(float c[4], const uint32_t a[4],
                                         const uint32_t b[2]) {
    asm volatile(
        "mma.sync.aligned.m16n8k8.row.col.f32.tf32.tf32.f32 "
        "{%0,%1,%2,%3}, {%4,%5,%6,%7}, {%8,%9}, {%0,%1,%2,%3};"
        : "+f"(c[0]), "+f"(c[1]), "+f"(c[2]), "+f"(c[3])
        : "r"(a[0]), "r"(a[1]), "r"(a[2]), "r"(a[3]), "r"(b[0]), "r"(b[1]));
}

#define CP16(dst, src) \
    asm volatile("cp.async.cg.shared.global [%0], [%1], 16;" \
                 :: "r"(dst), "l"(src) : "memory")

// fragment-packed word index within a 128x32 A tile (4096 words)
__device__ __forceinline__ int inner_a(int m, int k) {
    return ((m >> 4) * 4 + (k >> 3)) * 128 + (m & 7) * 16 + (k & 3) * 4 +
           ((k >> 2) & 1) * 2 + ((m >> 3) & 1);
}
// fragment-packed word index within a 128x32 B tile (4096 words)
__device__ __forceinline__ int inner_b(int n, int k) {
    return ((n >> 3) * 4 + (k >> 3)) * 64 + (n & 7) * 8 + (k & 3) * 2 +
           ((k >> 2) & 1);
}

// ---------------- operand pack kernels (fp32 -> fragment-packed tf32) ------
__global__ void pack_a_kernel(const float* __restrict__ src, uint32_t* __restrict__ dst,
                              int M, int K)
{
    int idx = blockIdx.x * blockDim.x + threadIdx.x;
    if (idx >= M * K) return;
    int row = idx / K;
    int k = idx - row * K;
    size_t tile = (size_t)(row >> 7) * (K >> 5) + (k >> 5);
    dst[tile * 4096 + inner_a(row & 127, k & 31)] = f2tf32(src[idx]);
}

__global__ void pack_b_kernel(const float* __restrict__ src, uint32_t* __restrict__ dst,
                              int N, int Npad, int K)
{
    int idx = blockIdx.x * blockDim.x + threadIdx.x;
    if (idx >= Npad * K) return;
    int n = idx / K;
    int k = idx - n * K;
    float v = (n < N) ? src[(size_t)n * K + k] : 0.f;
    size_t tile = (size_t)(n >> 7) * (K >> 5) + (k >> 5);
    dst[tile * 4096 + inner_b(n & 127, k & 31)] = f2tf32(v);
}

// ---------------- pipelined tensor-core tf32 GEMM on packed tiles ----------
// C[M,N] = A[M,K] @ B[N,K]^T. Grid: (N/128, M/128, splitZ).
// act: 0=none, 1=softplus(v+bias). atomic: accumulate with atomicAdd.
__global__ __launch_bounds__(256)
void gemm_mma_p(const uint32_t* __restrict__ Ap,
                const uint32_t* __restrict__ Bp,
                float* __restrict__ C, int ldc,
                int nKtiles, int ktCnt, int N,
                const float* __restrict__ bias, int act, int atomic)
{
    extern __shared__ uint32_t smem[];   // 2 * 8192 words = 64 KB

    const int tid = threadIdx.x;
    const int wid = tid >> 5;
    const int lane = tid & 31;
    const int warp_m = wid >> 2;          // 0..1
    const int warp_n = wid & 3;           // 0..3
    const int ktBeg = blockIdx.z * ktCnt;

    const uint32_t* gA = Ap + ((size_t)blockIdx.y * nKtiles + ktBeg) * 4096;
    const uint32_t* gB = Bp + ((size_t)blockIdx.x * nKtiles + ktBeg) * 4096;
    const uint32_t sbase = smem_u32(smem);

    float acc[4][4][4];
#pragma unroll
    for (int mi = 0; mi < 4; mi++)
#pragma unroll
        for (int ni = 0; ni < 4; ni++)
#pragma unroll
            for (int e = 0; e < 4; e++) acc[mi][ni][e] = 0.f;

    // stage copy: 16 KB A + 16 KB B per stage; 8 x 16B cp.async per thread
#define ISSUE_STAGE(s) do { \
    int _buf = (s) & 1; \
    uint32_t _dA = sbase + _buf * 32768 + tid * 16; \
    const char* _sA = (const char*)(gA + (size_t)(s) * 4096) + tid * 16; \
    const char* _sB = (const char*)(gB + (size_t)(s) * 4096) + tid * 16; \
    CP16(_dA + 0 * 4096, _sA + 0 * 4096); \
    CP16(_dA + 1 * 4096, _sA + 1 * 4096); \
    CP16(_dA + 2 * 4096, _sA + 2 * 4096); \
    CP16(_dA + 3 * 4096, _sA + 3 * 4096); \
    CP16(_dA + 16384 + 0 * 4096, _sB + 0 * 4096); \
    CP16(_dA + 16384 + 1 * 4096, _sB + 1 * 4096); \
    CP16(_dA + 16384 + 2 * 4096, _sB + 2 * 4096); \
    CP16(_dA + 16384 + 3 * 4096, _sB + 3 * 4096); \
    asm volatile("cp.async.commit_group;" ::: "memory"); \
} while (0)

    ISSUE_STAGE(0);
    for (int s = 0; s < ktCnt; s++) {
        if (s + 1 < ktCnt) {
            ISSUE_STAGE(s + 1);
            asm volatile("cp.async.wait_group 1;" ::: "memory");
        } else {
            asm volatile("cp.async.wait_group 0;" ::: "memory");
        }
        __syncthreads();

        const uint32_t* sA = smem + (s & 1) * 8192;
        const uint32_t* sB = sA + 4096;
#pragma unroll
        for (int kc = 0; kc < 4; kc++) {
            uint4 af[4];
            uint2 bf[4];
#pragma unroll
            for (int mi = 0; mi < 4; mi++)
                af[mi] = *(const uint4*)&sA[((warp_m * 4 + mi) * 4 + kc) * 128 + lane * 4];
#pragma unroll
            for (int ni = 0; ni < 4; ni++)
                bf[ni] = *(const uint2*)&sB[((warp_n * 4 + ni) * 4 + kc) * 64 + lane * 2];
#pragma unroll
            for (int mi = 0; mi < 4; mi++)
#pragma unroll
                for (int ni = 0; ni < 4; ni++)
                    mma_tf32(acc[mi][ni], (const uint32_t*)&af[mi],
                             (const uint32_t*)&bf[ni]);
        }
        __syncthreads();
    }
#undef ISSUE_STAGE

    // ---- epilogue ----
    const int r_lo = blockIdx.y * 128 + warp_m * 64 + (lane >> 2);
    const int c_lo = blockIdx.x * 128 + warp_n * 32 + (lane & 3) * 2;
    if (atomic) {
#pragma unroll
        for (int mi = 0; mi < 4; mi++) {
#pragma unroll
            for (int ni = 0; ni < 4; ni++) {
                int row = r_lo + mi * 16;
                int col = c_lo + ni * 8;
                if (col < N) {
                    atomicAdd(C + (size_t)row * ldc + col, acc[mi][ni][0]);
                    atomicAdd(C + (size_t)(row + 8) * ldc + col, acc[mi][ni][2]);
                }
                if (col + 1 < N) {
                    atomicAdd(C + (size_t)row * ldc + col + 1, acc[mi][ni][1]);
                    atomicAdd(C + (size_t)(row + 8) * ldc + col + 1, acc[mi][ni][3]);
                }
            }
        }
    } else {
#pragma unroll
        for (int mi = 0; mi < 4; mi++) {
#pragma unroll
            for (int ni = 0; ni < 4; ni++) {
                int row = r_lo + mi * 16;
                int col = c_lo + ni * 8;
                float v0 = acc[mi][ni][0], v1 = acc[mi][ni][1];
                float v2 = acc[mi][ni][2], v3 = acc[mi][ni][3];
                if (bias) {
                    float b0 = bias[col], b1 = bias[col + 1];
                    v0 += b0; v1 += b1; v2 += b0; v3 += b1;
                }
                if (act == 1) {
                    v0 = (v0 > 20.f) ? v0 : log1pf(__expf(v0));
                    v1 = (v1 > 20.f) ? v1 : log1pf(__expf(v1));
                    v2 = (v2 > 20.f) ? v2 : log1pf(__expf(v2));
                    v3 = (v3 > 20.f) ? v3 : log1pf(__expf(v3));
                }
                *(float2*)(C + (size_t)row * ldc + col) = make_float2(v0, v1);
                *(float2*)(C + (size_t)(row + 8) * ldc + col) = make_float2(v2, v3);
            }
        }
    }
}

// ---------------- zero g_xdbl (for split-K atomic accumulation) -------------
__global__ void zero_xdbl_kernel()
{
    int idx = blockIdx.x * blockDim.x + threadIdx.x;
    if (idx < NROWS * NDBL) g_xdbl[idx] = 0.f;
}

// ---------------- apply text gate; pack gated dt for G3 ----------------
__global__ void gate_apply_kernel()
{
    int idx = blockIdx.x * blockDim.x + threadIdx.x;
    if (idx >= NROWS * NDBL) return;
    int row = idx / NDBL;
    int j = idx - row * NDBL;
    int batch = row >> 10;
    float v = g_xdbl[idx] * g_gate[batch * NDBL + j];
    g_xdbl[idx] = v;
    if (j < DT_RANK) {
        size_t tile = (size_t)(row >> 7) * 2 + (j >> 5);
        g_dt_p[tile * 4096 + inner_a(row & 127, j & 31)] = f2tf32(v);
    }
}

// ---------------- causal depthwise conv (k=4) + SiLU + pack ----------------
__global__ void conv_silu_kernel(const float* __restrict__ conv_w,
                                 const float* __restrict__ conv_b)
{
    int idx = blockIdx.x * blockDim.x + threadIdx.x;
    int total = BATCH * SEQLEN * D_INNER;
    if (idx >= total) return;
    int d = idx & (D_INNER - 1);
    int l = (idx >> 11) & (SEQLEN - 1);
    int b = idx >> 21;

    float w0 = conv_w[d * 4 + 0], w1 = conv_w[d * 4 + 1];
    float w2 = conv_w[d * 4 + 2], w3 = conv_w[d * 4 + 3];
    const float* xrow = g_xz + ((size_t)(b * SEQLEN) * (2 * D_INNER)) + d;
    float acc = conv_b[d];
    if (l >= 3) acc += xrow[(size_t)(l - 3) * (2 * D_INNER)] * w0;
    if (l >= 2) acc += xrow[(size_t)(l - 2) * (2 * D_INNER)] * w1;
    if (l >= 1) acc += xrow[(size_t)(l - 1) * (2 * D_INNER)] * w2;
    acc += xrow[(size_t)l * (2 * D_INNER)] * w3;
    float s = acc / (1.f + __expf(-acc));
    int row = b * SEQLEN + l;
    g_xc[(size_t)row * D_INNER + d] = s;
    size_t tile = (size_t)(row >> 7) * (D_INNER >> 5) + (d >> 5);
    g_xc_p[tile * 4096 + inner_a(row & 127, d & 31)] = f2tf32(s);
}

// ---------------- text gate: sigmoid(x_text @ gate_w^T + gate_b) ------------
__global__ void gate_kernel(const float* __restrict__ x_text,
                            const float* __restrict__ gate_w,
                            const float* __restrict__ gate_b)
{
    int t = threadIdx.x;             // 0..191
    if (t >= BATCH * NDBL) return;
    int b = t / NDBL;
    int j = t % NDBL;
    const float* xr = x_text + b * D_MODEL;
    const float* wr = gate_w + (size_t)j * D_MODEL;
    float acc = gate_b[j];
    for (int k = 0; k < D_MODEL; k += 4) {
        float4 xv = *(const float4*)(xr + k);
        float4 wv = *(const float4*)(wr + k);
        acc += xv.x * wv.x + xv.y * wv.y + xv.z * wv.z + xv.w * wv.w;
    }
    g_gate[b * NDBL + j] = 1.f / (1.f + __expf(-acc));
}

// ---------------- selective scan + fused epilogue; writes y packed ----------
__global__ __launch_bounds__(256) void scan_kernel(const float* __restrict__ A_log,
                                                   const float* __restrict__ Dp)
{
    int g = blockIdx.x * blockDim.x + threadIdx.x;  // 0..65535
    int n = g & 15;
    int pair = g >> 4;
    int d = pair & (D_INNER - 1);
    int b = pair >> 11;

    float An = -__expf(A_log[d * D_STATE + n]);
    float Dd = Dp[d];
    float h = 0.f;

    const float* dptr = g_delta + (size_t)b * SEQLEN * D_INNER + d;
    const float* uptr = g_xc + (size_t)b * SEQLEN * D_INNER + d;
    const float* bcp = g_xdbl + (size_t)b * SEQLEN * NDBL + DT_RANK;
    const float* zptr = g_xz + (size_t)b * SEQLEN * (2 * D_INNER) + D_INNER + d;

    // constant parts of packed-y index (k = d & 31 fixed)
    const int ik = d & 31;
    const size_t kpart = (size_t)(d >> 5) * 4096 +
                         (ik >> 3) * 128 + (ik & 3) * 4 + ((ik >> 2) & 1) * 2;

    float dl = dptr[0];
    float u = uptr[0];
    float Bn = bcp[n];
    float Cn = bcp[D_STATE + n];

    for (int t = 0; t < SEQLEN; t++) {
        float dl_c = dl, u_c = u, Bn_c = Bn, Cn_c = Cn;
        if (t + 1 < SEQLEN) {
            size_t o = (size_t)(t + 1);
            dl = dptr[o * D_INNER];
            u = uptr[o * D_INNER];
            Bn = bcp[o * NDBL + n];
            Cn = bcp[o * NDBL + D_STATE + n];
        }
        float a = __expf(dl_c * An);
        h = h * a + dl_c * u_c * Bn_c;
        float p = h * Cn_c;
        p += __shfl_xor_sync(0xffffffffu, p, 8, 16);
        p += __shfl_xor_sync(0xffffffffu, p, 4, 16);
        p += __shfl_xor_sync(0xffffffffu, p, 2, 16);
        p += __shfl_xor_sync(0xffffffffu, p, 1, 16);
        if (n == 0) {
            float z = zptr[(size_t)t * (2 * D_INNER)];
            float sz = z / (1.f + __expf(-z));
            float yv = (p + Dd * u_c) * sz;
            int m = t & 127;
            size_t w = ((size_t)(b * 8 + (t >> 7)) * 64) * 4096 + kpart +
                       (m >> 4) * 512 + (m & 7) * 16 + ((m >> 3) & 1);
            g_y_p[w] = f2tf32(yv);
        }
    }
}

// ---------------- launcher ----------------
extern "C" void kernel_launch(void* const* d_in, const int* in_sizes, int n_in,
                              void* d_out, int out_size)
{
    const float* hidden    = (const float*)d_in[0];
    const float* x_text    = (const float*)d_in[1];
    const float* in_proj_w = (const float*)d_in[2];
    const float* conv_w    = (const float*)d_in[3];
    const float* conv_b    = (const float*)d_in[4];
    const float* x_proj_w  = (const float*)d_in[5];
    const float* dt_proj_w = (const float*)d_in[6];
    const float* dt_proj_b = (const float*)d_in[7];
    const float* A_log     = (const float*)d_in[8];
    const float* Dp        = (const float*)d_in[9];
    const float* out_proj_w= (const float*)d_in[10];
    const float* gate_w    = (const float*)d_in[11];
    const float* gate_b    = (const float*)d_in[12];
    float* out = (float*)d_out;

    static bool attr_set = false;
    if (!attr_set) {
        cudaFuncSetAttribute(gemm_mma_p,
                             cudaFuncAttributeMaxDynamicSharedMemorySize, 65536);
        attr_set = true;
    }

    float *xz, *xdbl, *delta;
    uint32_t *hid_p, *w1_p, *xc_p, *w2_p, *dt_p, *w3_p, *y_p, *w4_p;
    cudaGetSymbolAddress((void**)&xz, g_xz);
    cudaGetSymbolAddress((void**)&xdbl, g_xdbl);
    cudaGetSymbolAddress((void**)&delta, g_delta);
    cudaGetSymbolAddress((void**)&hid_p, g_hid_p);
    cudaGetSymbolAddress((void**)&w1_p, g_w1_p);
    cudaGetSymbolAddress((void**)&xc_p, g_xc_p);
    cudaGetSymbolAddress((void**)&w2_p, g_w2_p);
    cudaGetSymbolAddress((void**)&dt_p, g_dt_p);
    cudaGetSymbolAddress((void**)&w3_p, g_w3_p);
    cudaGetSymbolAddress((void**)&y_p, g_y_p);
    cudaGetSymbolAddress((void**)&w4_p, g_w4_p);

    const size_t SMEM = 65536;

    // pack G1 operands
    pack_a_kernel<<<(NROWS * D_MODEL + 255) / 256, 256>>>(hidden, hid_p, NROWS, D_MODEL);
    pack_b_kernel<<<(2 * D_INNER * D_MODEL + 255) / 256, 256>>>(in_proj_w, w1_p,
                                                                2 * D_INNER, 2 * D_INNER, D_MODEL);
    // pack weights for later GEMMs (independent of data flow)
    pack_b_kernel<<<(128 * D_INNER + 255) / 256, 256>>>(x_proj_w, w2_p, NDBL, 128, D_INNER);
    pack_b_kernel<<<(D_INNER * DT_RANK + 255) / 256, 256>>>(dt_proj_w, w3_p,
                                                            D_INNER, D_INNER, DT_RANK);
    pack_b_kernel<<<(D_MODEL * D_INNER + 255) / 256, 256>>>(out_proj_w, w4_p,
                                                            D_MODEL, D_MODEL, D_INNER);
    gate_kernel<<<1, 192>>>(x_text, gate_w, gate_b);

    // G1: xz = hidden @ in_proj_w^T  (2048 x 4096, K=1024)
    {
        dim3 grid(2 * D_INNER / 128, NROWS / 128, 1);
        gemm_mma_p<<<grid, 256, SMEM>>>(hid_p, w1_p, xz, 2 * D_INNER,
                                        D_MODEL / 32, D_MODEL / 32, 2 * D_INNER,
                                        nullptr, 0, 0);
    }
    // conv + silu (+ pack xc)
    {
        int total = BATCH * SEQLEN * D_INNER;
        conv_silu_kernel<<<(total + 255) / 256, 256>>>(conv_w, conv_b);
    }
    zero_xdbl_kernel<<<(NROWS * NDBL + 255) / 256, 256>>>();
    // G2: x_dbl = xc @ x_proj_w^T  (2048 x 96, K=2048) split-K=8, atomic
    {
        dim3 grid(1, NROWS / 128, 8);
        gemm_mma_p<<<grid, 256, SMEM>>>(xc_p, w2_p, xdbl, NDBL,
                                        D_INNER / 32, (D_INNER / 32) / 8, NDBL,
                                        nullptr, 0, 1);
    }
    // apply text gate (+ pack gated dt)
    gate_apply_kernel<<<(NROWS * NDBL + 255) / 256, 256>>>();
    // G3: delta = softplus(dt @ dt_proj_w^T + dt_proj_b)  (2048 x 2048, K=64)
    {
        dim3 grid(D_INNER / 128, NROWS / 128, 1);
        gemm_mma_p<<<grid, 256, SMEM>>>(dt_p, w3_p, delta, D_INNER,
                                        DT_RANK / 32, DT_RANK / 32, D_INNER,
                                        dt_proj_b, 1, 0);
    }
    // scan + fused (D*xc, silu(z)) epilogue; writes y packed
    scan_kernel<<<(BATCH * D_INNER * D_STATE) / 256, 256>>>(A_log, Dp);
    // G4: out = y @ out_proj_w^T  (2048 x 1024, K=2048)
    {
        dim3 grid(D_MODEL / 128, NROWS / 128, 1);
        gemm_mma_p<<<grid, 256, SMEM>>>(y_p, w4_p, out, D_MODEL,
                                        D_INNER / 32, D_INNER / 32, D_MODEL,
                                        nullptr, 0, 0);
    }
}